// round 10
// baseline (speedup 1.0000x reference)
#include <cuda_runtime.h>
#include <math.h>
#include <float.h>

#define BB 2
#define SEQ 2048
#define DIM 1024
#define FF 2816
#define NTOK (BB*SEQ)
#define WIN 512
#define OUTV 32000
#define SPACE 36
#define QKVS 3072
#define FF2  5632

#define DD   (DIM*DIM)          // 1048576
#define DF   (DIM*FF)           // 2883584
#define LWS  (4*DD + 3*DF)      // per-layer weight floats
#define WTOT (2*LWS + DIM*OUTV) // all rounded weights

// ---------------- scratch (device globals; no allocation allowed) ----------------
__device__ float g_embeds[NTOK*DIM];
__device__ float g_h[NTOK*DIM];
__device__ float g_xn[NTOK*DIM];
__device__ float g_qkv[(size_t)NTOK*QKVS];
__device__ float g_attn[NTOK*DIM];
__device__ float g_f13[(size_t)NTOK*FF2];
__device__ float g_f1[(size_t)NTOK*FF];
__device__ float g_pool[NTOK*DIM];
__device__ float g_wt[WTOT];
__device__ int   g_pid[NTOK];
__device__ int   g_pstart[NTOK];
__device__ int   g_np[BB];

__device__ __forceinline__ float rtf(float x){
    unsigned r;
    asm("cvt.rna.tf32.f32 %0, %1;" : "=r"(r) : "f"(x));
    return __uint_as_float(r);
}

// ---------------- round fp32 -> tf32-snapped fp32, with column-packing ----------------
__global__ __launch_bounds__(256) void k_round(const float* __restrict__ s,
        float* __restrict__ d, int n4, int ncols4, int totcols4, int coloff4){
    int stride = gridDim.x * 256;
    int e = blockIdx.x*256 + threadIdx.x;
    float4 v[4]; int idx[4]; int cnt = 0;
    #pragma unroll
    for (int i = 0; i < 4; i++){
        int ix = e + i*stride;
        if (ix < n4){ v[cnt] = ((const float4*)s)[ix]; idx[cnt] = ix; cnt++; }
    }
    #pragma unroll
    for (int i = 0; i < 4; i++){
        if (i < cnt){
            float4 w = v[i];
            w.x = rtf(w.x); w.y = rtf(w.y); w.z = rtf(w.z); w.w = rtf(w.w);
            int k = idx[i] / ncols4;
            int c = idx[i] - k*ncols4;
            ((float4*)d)[(size_t)k*totcols4 + coloff4 + c] = w;
        }
    }
}

// ---------------- hash n-gram embeddings ----------------
__global__ __launch_bounds__(256) void k_hash_embed(const int* __restrict__ ids,
        const float* __restrict__ tok_emb, const float* __restrict__ hash_emb){
    int bs = blockIdx.x; int b = bs / SEQ; int i = bs - b*SEQ;
    const int* row = ids + b*SEQ;
    unsigned gg[4];
    #pragma unroll
    for (int j = 0; j < 4; j++) gg[j] = (i >= j) ? (unsigned)row[i-j] : 0u;
    const unsigned mult[3] = {2654435761u, 805459861u, 2246822519u};
    const float* src0 = tok_emb + (size_t)row[i]*DIM;
    const float* srch[3];
    #pragma unroll
    for (int f = 0; f < 3; f++){
        unsigned a = mult[f], h = 0u;
        #pragma unroll
        for (int j = 0; j < 4; j++) h = h*a + gg[j];
        srch[f] = hash_emb + ((size_t)f*32000u + (h % 32000u))*DIM;
    }
    int d = threadIdx.x*4;
    float4 v = *(const float4*)(src0 + d);
    #pragma unroll
    for (int f = 0; f < 3; f++){
        float4 w = *(const float4*)(srch[f] + d);
        v.x += w.x; v.y += w.y; v.z += w.z; v.w += w.w;
    }
    size_t o = (size_t)bs*DIM + d;
    *(float4*)(g_embeds + o) = v;
    *(float4*)(g_h + o) = v;
}

// ---------------- patch ids via warp scan (1 warp per batch) ----------------
__global__ void k_patch(const int* __restrict__ ids){
    int b = threadIdx.x >> 5;
    int lane = threadIdx.x & 31;
    if (b >= BB) return;
    const int* row = ids + b*SEQ;
    int base = 0;
    for (int c = 0; c < SEQ; c += 32){
        int i = c + lane;
        int s = (i == 0) || (row[i-1] == SPACE);
        unsigned m = __ballot_sync(0xffffffffu, s);
        int pid = base + __popc(m & (0xffffffffu >> (31 - lane))) - 1;
        g_pid[b*SEQ + i] = pid;
        if (s) g_pstart[b*SEQ + pid] = i;
        base += __popc(m);
    }
    if (lane == 0) g_np[b] = base;
}

// ---------------- rmsnorm: g_h -> g_xn (output tf32-snapped) ----------------
__global__ __launch_bounds__(256) void k_rmsnorm(const float* __restrict__ w){
    int rowi = blockIdx.x;
    int tid = threadIdx.x;
    size_t base = (size_t)rowi*DIM + tid*4;
    float4 v = *(const float4*)(g_h + base);
    float ss = v.x*v.x + v.y*v.y + v.z*v.z + v.w*v.w;
    #pragma unroll
    for (int o = 16; o; o >>= 1) ss += __shfl_xor_sync(0xffffffffu, ss, o);
    __shared__ float red[8];
    if ((tid & 31) == 0) red[tid >> 5] = ss;
    __syncthreads();
    float tot = red[0]+red[1]+red[2]+red[3]+red[4]+red[5]+red[6]+red[7];
    float r = rsqrtf(tot * (1.0f/DIM) + 1e-5f);
    float4 wv = *(const float4*)(w + tid*4);
    float4 o4;
    o4.x = rtf(v.x*r*wv.x); o4.y = rtf(v.y*r*wv.y);
    o4.z = rtf(v.z*r*wv.z); o4.w = rtf(v.w*r*wv.w);
    *(float4*)(g_xn + base) = o4;
}

#define CP_ASYNC16(dst, src) \
    asm volatile("cp.async.cg.shared.global [%0], [%1], 16;\n" :: "r"(dst), "l"(src))
#define CP_COMMIT() asm volatile("cp.async.commit_group;\n" ::)

#define MMA_TF32(acc, a0,a1,a2,a3, b0,b1) \
    asm volatile( \
        "mma.sync.aligned.m16n8k8.row.col.f32.tf32.tf32.f32 " \
        "{%0,%1,%2,%3}, {%4,%5,%6,%7}, {%8,%9}, {%0,%1,%2,%3};" \
        : "+f"((acc)[0]), "+f"((acc)[1]), "+f"((acc)[2]), "+f"((acc)[3]) \
        : "r"(a0), "r"(a1), "r"(a2), "r"(a3), "r"(b0), "r"(b1))

// ---------------- tf32 GEMM, 128x128 tile (used for N=1024 GEMMs with residual) ----------------
#define GSMEM (4*(128*20 + 16*136)*4)

__global__ __launch_bounds__(256, 2) void k_gemm(const float* __restrict__ A,
        const float* __restrict__ Bm, float* __restrict__ C,
        const float* __restrict__ R, int N, int K, int addres){
    extern __shared__ __align__(16) float smem[];
    float (*As)[128][20] = (float(*)[128][20])smem;
    float (*Bs)[16][136] = (float(*)[16][136])(smem + 4*128*20);

    const int m0 = blockIdx.x * 128, n0 = blockIdx.y * 128;
    const int tid = threadIdx.x;
    const int wid = tid >> 5, lane = tid & 31;
    const int wm = (wid >> 2) * 64;
    const int wn = (wid & 3) * 32;
    const int g = lane >> 2, tg = lane & 3;

    const int arow = tid >> 2, acol = (tid & 3) * 4;
    const int brow = tid >> 5, bcol = (tid & 31) * 4;
    const float* Abase = A + (size_t)(m0 + arow)*K + acol;
    const float* Bbase = Bm + (size_t)brow*N + n0 + bcol;

    float acc[4][4][4];
    #pragma unroll
    for (int i = 0; i < 4; i++)
        #pragma unroll
        for (int j = 0; j < 4; j++)
            #pragma unroll
            for (int c = 0; c < 4; c++) acc[i][j][c] = 0.0f;

#define LOADSTAGE(st, k0) do { \
        unsigned da0 = (unsigned)__cvta_generic_to_shared(&As[st][arow][acol]); \
        CP_ASYNC16(da0, Abase + (k0)); \
        unsigned da1 = (unsigned)__cvta_generic_to_shared(&As[st][arow+64][acol]); \
        CP_ASYNC16(da1, Abase + (size_t)64*K + (k0)); \
        unsigned db0 = (unsigned)__cvta_generic_to_shared(&Bs[st][brow][bcol]); \
        CP_ASYNC16(db0, Bbase + (size_t)(k0)*N); \
        unsigned db1 = (unsigned)__cvta_generic_to_shared(&Bs[st][brow+8][bcol]); \
        CP_ASYNC16(db1, Bbase + (size_t)((k0)+8)*N); \
        CP_COMMIT(); \
    } while(0)

    const int KT = K >> 4;
    LOADSTAGE(0, 0);
    LOADSTAGE(1, 16);
    LOADSTAGE(2, 32);

    for (int kt = 0; kt < KT; kt++){
        const int s = kt & 3;
        const int rem = KT - 1 - kt;
        if (rem >= 2)      asm volatile("cp.async.wait_group 2;\n" ::);
        else if (rem == 1) asm volatile("cp.async.wait_group 1;\n" ::);
        else               asm volatile("cp.async.wait_group 0;\n" ::);
        __syncthreads();
        if (kt + 3 < KT) LOADSTAGE((kt+3) & 3, (kt+3) << 4);

        #pragma unroll
        for (int kk = 0; kk < 16; kk += 8){
            unsigned af[4][4], bf[4][2];
            #pragma unroll
            for (int i = 0; i < 4; i++){
                int r = wm + i*16;
                af[i][0] = __float_as_uint(As[s][r+g   ][kk+tg  ]);
                af[i][1] = __float_as_uint(As[s][r+g+8 ][kk+tg  ]);
                af[i][2] = __float_as_uint(As[s][r+g   ][kk+tg+4]);
                af[i][3] = __float_as_uint(As[s][r+g+8 ][kk+tg+4]);
            }
            #pragma unroll
            for (int j = 0; j < 4; j++){
                int cl = wn + j*8 + g;
                bf[j][0] = __float_as_uint(Bs[s][kk+tg  ][cl]);
                bf[j][1] = __float_as_uint(Bs[s][kk+tg+4][cl]);
            }
            #pragma unroll
            for (int i = 0; i < 4; i++)
                #pragma unroll
                for (int j = 0; j < 4; j++)
                    MMA_TF32(acc[i][j], af[i][0],af[i][1],af[i][2],af[i][3],
                             bf[j][0],bf[j][1]);
        }
    }

    #pragma unroll
    for (int i = 0; i < 4; i++){
        #pragma unroll
        for (int j = 0; j < 4; j++){
            size_t off = (size_t)(m0 + wm + i*16 + g)*N + n0 + wn + j*8 + tg*2;
            float2 r0 = make_float2(acc[i][j][0], acc[i][j][1]);
            float2 r1 = make_float2(acc[i][j][2], acc[i][j][3]);
            if (addres){
                float2 q0 = *(const float2*)(R + off);
                float2 q1 = *(const float2*)(R + off + (size_t)8*N);
                r0.x += q0.x; r0.y += q0.y; r1.x += q1.x; r1.y += q1.y;
            }
            *(float2*)(C + off) = r0;
            *(float2*)(C + off + (size_t)8*N) = r1;
        }
    }
}

// ---------------- tf32 GEMM, 256x128 tile, 64x64 warp tiles (large-N, no residual) ----------------
// Halves fragment-load redundancy: 32 LDS per 32 MMA per warp-slice -> crossbar no
// longer co-saturated with the tensor pipe. 1 CTA/SM (114 KB smem, ~185 regs).
#define GSMEM2 (4*(256*20 + 16*136)*4)

__global__ __launch_bounds__(256, 1) void k_gemm2(const float* __restrict__ A,
        const float* __restrict__ Bm, float* __restrict__ C, int N, int K){
    extern __shared__ __align__(16) float smem[];
    float (*As)[256][20] = (float(*)[256][20])smem;
    float (*Bs)[16][136] = (float(*)[16][136])(smem + 4*256*20);

    const int m0 = blockIdx.x * 256, n0 = blockIdx.y * 128;
    const int tid = threadIdx.x;
    const int wid = tid >> 5, lane = tid & 31;
    const int wm = (wid >> 1) * 64;          // 4 m-groups
    const int wn = (wid & 1) * 64;           // 2 n-groups
    const int g = lane >> 2, tg = lane & 3;

    const int brow = tid >> 4, bcol = (tid & 15) * 8;
    const float* Abase = A + (size_t)(m0 + tid)*K;
    const float* Bbase = Bm + (size_t)brow*N + n0 + bcol;

    float acc[4][8][4];
    #pragma unroll
    for (int i = 0; i < 4; i++)
        #pragma unroll
        for (int j = 0; j < 8; j++)
            #pragma unroll
            for (int c = 0; c < 4; c++) acc[i][j][c] = 0.0f;

#define LOADSTAGE2(st, k0) do { \
        _Pragma("unroll") \
        for (int jj = 0; jj < 4; jj++){ \
            unsigned da = (unsigned)__cvta_generic_to_shared(&As[st][tid][jj*4]); \
            CP_ASYNC16(da, Abase + (k0) + jj*4); \
        } \
        unsigned db0 = (unsigned)__cvta_generic_to_shared(&Bs[st][brow][bcol]); \
        CP_ASYNC16(db0, Bbase + (size_t)(k0)*N); \
        unsigned db1 = (unsigned)__cvta_generic_to_shared(&Bs[st][brow][bcol+4]); \
        CP_ASYNC16(db1, Bbase + (size_t)(k0)*N + 4); \
        CP_COMMIT(); \
    } while(0)

    const int KT = K >> 4;
    LOADSTAGE2(0, 0);
    LOADSTAGE2(1, 16);
    LOADSTAGE2(2, 32);

    for (int kt = 0; kt < KT; kt++){
        const int s = kt & 3;
        const int rem = KT - 1 - kt;
        if (rem >= 2)      asm volatile("cp.async.wait_group 2;\n" ::);
        else if (rem == 1) asm volatile("cp.async.wait_group 1;\n" ::);
        else               asm volatile("cp.async.wait_group 0;\n" ::);
        __syncthreads();
        if (kt + 3 < KT) LOADSTAGE2((kt+3) & 3, (kt+3) << 4);

        #pragma unroll
        for (int kk = 0; kk < 16; kk += 8){
            unsigned af[4][4], bf[8][2];
            #pragma unroll
            for (int i = 0; i < 4; i++){
                int r = wm + i*16;
                af[i][0] = __float_as_uint(As[s][r+g   ][kk+tg  ]);
                af[i][1] = __float_as_uint(As[s][r+g+8 ][kk+tg  ]);
                af[i][2] = __float_as_uint(As[s][r+g   ][kk+tg+4]);
                af[i][3] = __float_as_uint(As[s][r+g+8 ][kk+tg+4]);
            }
            #pragma unroll
            for (int j = 0; j < 8; j++){
                int cl = wn + j*8 + g;
                bf[j][0] = __float_as_uint(Bs[s][kk+tg  ][cl]);
                bf[j][1] = __float_as_uint(Bs[s][kk+tg+4][cl]);
            }
            #pragma unroll
            for (int i = 0; i < 4; i++)
                #pragma unroll
                for (int j = 0; j < 8; j++)
                    MMA_TF32(acc[i][j], af[i][0],af[i][1],af[i][2],af[i][3],
                             bf[j][0],bf[j][1]);
        }
    }

    #pragma unroll
    for (int i = 0; i < 4; i++){
        #pragma unroll
        for (int j = 0; j < 8; j++){
            size_t off = (size_t)(m0 + wm + i*16 + g)*N + n0 + wn + j*8 + tg*2;
            *(float2*)(C + off) = make_float2(acc[i][j][0], acc[i][j][1]);
            *(float2*)(C + off + (size_t)8*N) = make_float2(acc[i][j][2], acc[i][j][3]);
        }
    }
}

// ---------------- RoPE (in place on q,k inside g_qkv) ----------------
__global__ __launch_bounds__(256) void k_rope(){
    int bs = blockIdx.x;
    int pos = bs & (SEQ - 1);
    size_t base = (size_t)bs*QKVS;
    for (int d = threadIdx.x; d < 512; d += 256){
        float freq = powf(10000.0f, -(float)d * (1.0f/512.0f));
        float ang = (float)pos * freq;
        float sn, cs;
        sincosf(ang, &sn, &cs);
        float x1 = g_qkv[base + d], x2 = g_qkv[base + 512 + d];
        g_qkv[base + d]       = x1*cs - x2*sn;
        g_qkv[base + 512 + d] = x1*sn + x2*cs;
        x1 = g_qkv[base + 1024 + d]; x2 = g_qkv[base + 1536 + d];
        g_qkv[base + 1024 + d] = x1*cs - x2*sn;
        g_qkv[base + 1536 + d] = x1*sn + x2*cs;
    }
}

// ---------------- fused windowed causal attention, 16-query tiles ----------------
#define QT 16
#define SPAN 544
__global__ __launch_bounds__(256) void k_attn(){
    __shared__ __align__(16) float Ssh[QT*SPAN];   // 34.8 KB
    __shared__ __align__(16) float stage[4752];    // 19 KB
    float* Qs = stage;            // [16][33]
    float* Ks = stage + 16*33;    // [128][33]
    float* Vs = stage;            // [32][136] in pass 2
    int tile = blockIdx.x;
    int b = tile / (SEQ/QT);
    int i0 = (tile - b*(SEQ/QT)) * QT;
    int tid = threadIdx.x;
    int tq = tid >> 5, tk = tid & 31;
    int kmin = i0 - (WIN - 1); if (kmin < 0) kmin = 0;
    int span = i0 + QT - kmin;                       // <= 527
    int spanw = ((span + 63) >> 6) << 6;
    if (spanw > SPAN) spanw = SPAN;
    int lastkey = i0 + QT - 1;

    // ---- pass 1: scores = Q K^T / 32 (banded, masked) ----
    for (int kc0 = 0; kc0 < span; kc0 += 128){
        float c[2][4] = {{0.f,0.f,0.f,0.f},{0.f,0.f,0.f,0.f}};
        for (int dc = 0; dc < DIM; dc += 32){
            int r = tid >> 3, cb = (tid & 7) << 2;
            if (tid < 128){
                float4 qv = *(const float4*)(g_qkv + ((size_t)(b*SEQ + i0 + r))*QKVS + dc + cb);
                float* qp = Qs + r*33 + cb;
                qp[0]=qv.x; qp[1]=qv.y; qp[2]=qv.z; qp[3]=qv.w;
            }
            #pragma unroll
            for (int h = 0; h < 4; h++){
                int rr = r + h*32;
                int key = kmin + kc0 + rr; if (key > lastkey) key = lastkey;
                float4 kv = *(const float4*)(g_qkv + ((size_t)(b*SEQ + key))*QKVS + 1024 + dc + cb);
                float* kp = Ks + rr*33 + cb;
                kp[0]=kv.x; kp[1]=kv.y; kp[2]=kv.z; kp[3]=kv.w;
            }
            __syncthreads();
            #pragma unroll
            for (int d = 0; d < 32; d++){
                float a0 = Qs[(tq*2)*33 + d];
                float a1 = Qs[(tq*2+1)*33 + d];
                #pragma unroll
                for (int v = 0; v < 4; v++){
                    float bv = Ks[(tk + 32*v)*33 + d];
                    c[0][v] += a0*bv;
                    c[1][v] += a1*bv;
                }
            }
            __syncthreads();
        }
        #pragma unroll
        for (int u = 0; u < 2; u++){
            int qa = i0 + tq*2 + u;
            #pragma unroll
            for (int v = 0; v < 4; v++){
                int jr = kc0 + tk + 32*v;
                if (jr < SPAN){
                    int ja = kmin + jr;
                    bool ok = (jr < span) && (ja <= qa) && (qa - ja < WIN);
                    Ssh[(tq*2+u)*SPAN + jr] = ok ? c[u][v]*0.03125f : -1e30f;
                }
            }
        }
    }
    __syncthreads();

    // ---- softmax (8 warps, 2 rows each) ----
    for (int q = tq; q < QT; q += 8){
        float* sr = Ssh + q*SPAN;
        float mx = -1e30f;
        for (int j = tk; j < spanw; j += 32) mx = fmaxf(mx, sr[j]);
        #pragma unroll
        for (int o = 16; o; o >>= 1) mx = fmaxf(mx, __shfl_xor_sync(0xffffffffu, mx, o));
        float sm = 0.f;
        for (int j = tk; j < spanw; j += 32){
            float p = expf(sr[j] - mx); sr[j] = p; sm += p;
        }
        #pragma unroll
        for (int o = 16; o; o >>= 1) sm += __shfl_xor_sync(0xffffffffu, sm, o);
        float inv = 1.0f/sm;
        for (int j = tk; j < spanw; j += 32) sr[j] *= inv;
    }
    __syncthreads();

    // ---- pass 2: O = P @ V (output tf32-snapped for the wo GEMM) ----
    for (int n0 = 0; n0 < DIM; n0 += 128){
        float o[2][4] = {{0.f,0.f,0.f,0.f},{0.f,0.f,0.f,0.f}};
        for (int kc0 = 0; kc0 < span; kc0 += 32){
            int r = tid >> 3, cb = (tid & 7) << 4;
            int key = kmin + kc0 + r; if (key > lastkey) key = lastkey;
            const float* vp = g_qkv + ((size_t)(b*SEQ + key))*QKVS + 2048 + n0 + cb;
            #pragma unroll
            for (int t4 = 0; t4 < 4; t4++){
                *(float4*)(Vs + r*136 + cb + t4*4) = *(const float4*)(vp + t4*4);
            }
            __syncthreads();
            const float* p0r = Ssh + (tq*2)*SPAN + kc0;
            const float* p1r = p0r + SPAN;
            #pragma unroll
            for (int jj = 0; jj < 32; jj++){
                float p0 = p0r[jj], p1 = p1r[jj];
                #pragma unroll
                for (int v = 0; v < 4; v++){
                    float vv = Vs[jj*136 + tk + 32*v];
                    o[0][v] += p0*vv;
                    o[1][v] += p1*vv;
                }
            }
            __syncthreads();
        }
        size_t ob = ((size_t)(b*SEQ + i0 + tq*2))*DIM + n0;
        #pragma unroll
        for (int v = 0; v < 4; v++){
            g_attn[ob + tk + 32*v]       = rtf(o[0][v]);
            g_attn[ob + DIM + tk + 32*v] = rtf(o[1][v]);
        }
    }
}

// ---------------- silu(f13[:, :FF]) * f13[:, FF:] -> f1 (tf32-snapped) ----------------
__global__ __launch_bounds__(704) void k_silu(){
    int row = blockIdx.x;
    int col = threadIdx.x * 4;
    size_t src = (size_t)row*FF2 + col;
    float4 a = *(float4*)(g_f13 + src);
    float4 c = *(float4*)(g_f13 + src + FF);
    a.x = rtf(a.x/(1.f + expf(-a.x))*c.x);
    a.y = rtf(a.y/(1.f + expf(-a.y))*c.y);
    a.z = rtf(a.z/(1.f + expf(-a.z))*c.z);
    a.w = rtf(a.w/(1.f + expf(-a.w))*c.w);
    *(float4*)(g_f1 + (size_t)row*FF + col) = a;
}

// ---------------- segment max pooling (runs are contiguous) ----------------
__global__ __launch_bounds__(256) void k_pool(){
    int b = blockIdx.y, p = blockIdx.x;
    int np = g_np[b];
    if (p >= np) return;
    int i0 = g_pstart[b*SEQ + p];
    int i1 = (p + 1 < np) ? g_pstart[b*SEQ + p + 1] : SEQ;
    int d = threadIdx.x*4;
    float4 m = make_float4(-FLT_MAX, -FLT_MAX, -FLT_MAX, -FLT_MAX);
    const float* src = g_xn + (size_t)b*SEQ*DIM + d;
    for (int i = i0; i < i1; i++){
        float4 v = *(const float4*)(src + (size_t)i*DIM);
        m.x = fmaxf(m.x, v.x); m.y = fmaxf(m.y, v.y);
        m.z = fmaxf(m.z, v.z); m.w = fmaxf(m.w, v.w);
    }
    *(float4*)(g_pool + ((size_t)(b*SEQ + p))*DIM + d) = m;
}

// ---------------- hd = embeds + pooled[pid]  -> g_h ----------------
__global__ __launch_bounds__(256) void k_gather(){
    int bs = blockIdx.x; int b = bs / SEQ;
    int pid = g_pid[bs];
    int d = threadIdx.x*4;
    size_t o = (size_t)bs*DIM + d;
    float4 e = *(const float4*)(g_embeds + o);
    float4 pl = *(const float4*)(g_pool + ((size_t)(b*SEQ + pid))*DIM + d);
    e.x += pl.x; e.y += pl.y; e.z += pl.z; e.w += pl.w;
    *(float4*)(g_h + o) = e;
}

// ---------------- host orchestration ----------------
extern "C" void kernel_launch(void* const* d_in, const int* in_sizes, int n_in,
                              void* d_out, int out_size){
    const int*   ids  = (const int*)d_in[0];
    const float* tok  = (const float*)d_in[1];
    const float* hemb = (const float*)d_in[2];

    float *p_xn, *p_qkv, *p_attn, *p_h, *p_f13, *p_f1, *p_wt;
    cudaGetSymbolAddress((void**)&p_xn,   g_xn);
    cudaGetSymbolAddress((void**)&p_qkv,  g_qkv);
    cudaGetSymbolAddress((void**)&p_attn, g_attn);
    cudaGetSymbolAddress((void**)&p_h,    g_h);
    cudaGetSymbolAddress((void**)&p_f13,  g_f13);
    cudaGetSymbolAddress((void**)&p_f1,   g_f1);
    cudaGetSymbolAddress((void**)&p_wt,   g_wt);

    static int smem_set = 0;
    if (!smem_set){
        cudaFuncSetAttribute(k_gemm,  cudaFuncAttributeMaxDynamicSharedMemorySize, GSMEM);
        cudaFuncSetAttribute(k_gemm2, cudaFuncAttributeMaxDynamicSharedMemorySize, GSMEM2);
        smem_set = 1;
    }

    // Round weights to tf32-snapped scratch; pack qkv -> [1024,3072], w1|w3 -> [1024,5632].
    #define RND(src, dstoff, ncols, totcols, coloff, nelem) do { \
        int _n4 = (nelem)/4; \
        int _grid = (_n4 + 256*4 - 1)/(256*4); \
        k_round<<<_grid, 256>>>((src), p_wt + (dstoff), _n4, (ncols)/4, (totcols)/4, (coloff)/4); \
    } while(0)
    for (int L = 0; L < 2; L++){
        size_t base = (size_t)L*LWS;
        RND((const float*)d_in[3+10*L+0], base,            DIM, QKVS, 0,        DD);  // wq
        RND((const float*)d_in[3+10*L+1], base,            DIM, QKVS, DIM,      DD);  // wk
        RND((const float*)d_in[3+10*L+2], base,            DIM, QKVS, 2*DIM,    DD);  // wv
        RND((const float*)d_in[3+10*L+3], base+3*DD,       DIM, DIM,  0,        DD);  // wo
        RND((const float*)d_in[3+10*L+4], base+4*DD,       FF,  FF2,  0,        DF);  // w1
        RND((const float*)d_in[3+10*L+6], base+4*DD,       FF,  FF2,  FF,       DF);  // w3
        RND((const float*)d_in[3+10*L+5], base+4*DD+2*(size_t)DF, DIM, DIM, 0,  DF);  // w2
    }
    RND((const float*)d_in[23], 2*(size_t)LWS, OUTV, OUTV, 0, (size_t)DIM*OUTV);

    k_hash_embed<<<NTOK, 256>>>(ids, tok, hemb);
    k_patch<<<1, 64>>>(ids);

    for (int L = 0; L < 2; L++){
        size_t base = (size_t)L*LWS;
        float* wqkv = p_wt + base;
        float* wo   = p_wt + base + 3*DD;
        float* w13  = p_wt + base + 4*DD;
        float* w2   = p_wt + base + 4*DD + 2*(size_t)DF;
        const float* natt = (const float*)d_in[3 + 10*L + 7];
        const float* nffn = (const float*)d_in[3 + 10*L + 8];
        const float* nout = (const float*)d_in[3 + 10*L + 9];

        k_rmsnorm<<<NTOK, 256>>>(natt);
        k_gemm2<<<dim3(16, 24), 256, GSMEM2>>>(p_xn, wqkv, p_qkv, QKVS, DIM);
        k_rope<<<NTOK, 256>>>();
        k_attn<<<NTOK/QT, 256>>>();
        k_gemm<<<dim3(32, 8),  256, GSMEM>>>(p_attn, wo, p_h, p_h, DIM, DIM, 1);
        k_rmsnorm<<<NTOK, 256>>>(nffn);
        k_gemm2<<<dim3(16, 44), 256, GSMEM2>>>(p_xn, w13, p_f13, FF2, DIM);
        k_silu<<<NTOK, 704>>>();
        k_gemm<<<dim3(32, 8),  256, GSMEM>>>(p_f1, w2, p_h, p_h, DIM, FF, 1);

        if (L == 0){
            k_rmsnorm<<<NTOK, 256>>>(nout);        // g_h -> g_xn (encoder out norm)
            k_pool<<<dim3(SEQ, BB), 256>>>();      // segment max over g_xn
            k_gather<<<NTOK, 256>>>();             // g_h = embeds + pooled[pid]
        }
    }
    k_rmsnorm<<<NTOK, 256>>>((const float*)d_in[22]);  // dec_norm_out
    k_gemm2<<<dim3(16, 250), 256, GSMEM2>>>(p_xn, p_wt + 2*(size_t)LWS, (float*)d_out,
                                            OUTV, DIM);
}

// round 11
// speedup vs baseline: 1.3742x; 1.3742x over previous
#include <cuda_runtime.h>
#include <math.h>
#include <float.h>

#define BB 2
#define SEQ 2048
#define DIM 1024
#define FF 2816
#define NTOK (BB*SEQ)
#define WIN 512
#define OUTV 32000
#define SPACE 36
#define QKVS 3072
#define FF2  5632

#define DD   (DIM*DIM)          // 1048576
#define DF   (DIM*FF)           // 2883584
#define LWS  (4*DD + 3*DF)      // per-layer weight floats
#define WTOT (2*LWS + DIM*OUTV) // all rounded weights

// ---------------- scratch (device globals; no allocation allowed) ----------------
__device__ float g_embeds[NTOK*DIM];
__device__ float g_h[NTOK*DIM];
__device__ float g_xn[NTOK*DIM];
__device__ float g_qkv[(size_t)NTOK*QKVS];
__device__ float g_attn[NTOK*DIM];
__device__ float g_f13[(size_t)NTOK*FF2];
__device__ float g_f1[(size_t)NTOK*FF];
__device__ float g_pool[NTOK*DIM];
__device__ float g_wt[WTOT];
__device__ int   g_pid[NTOK];
__device__ int   g_pstart[NTOK];
__device__ int   g_np[BB];

__device__ __forceinline__ float rtf(float x){
    unsigned r;
    asm("cvt.rna.tf32.f32 %0, %1;" : "=r"(r) : "f"(x));
    return __uint_as_float(r);
}

// ---------------- round fp32 -> tf32-snapped fp32, with column-packing ----------------
__global__ __launch_bounds__(256) void k_round(const float* __restrict__ s,
        float* __restrict__ d, int n4, int ncols4, int totcols4, int coloff4){
    int stride = gridDim.x * 256;
    int e = blockIdx.x*256 + threadIdx.x;
    float4 v[4]; int idx[4]; int cnt = 0;
    #pragma unroll
    for (int i = 0; i < 4; i++){
        int ix = e + i*stride;
        if (ix < n4){ v[cnt] = ((const float4*)s)[ix]; idx[cnt] = ix; cnt++; }
    }
    #pragma unroll
    for (int i = 0; i < 4; i++){
        if (i < cnt){
            float4 w = v[i];
            w.x = rtf(w.x); w.y = rtf(w.y); w.z = rtf(w.z); w.w = rtf(w.w);
            int k = idx[i] / ncols4;
            int c = idx[i] - k*ncols4;
            ((float4*)d)[(size_t)k*totcols4 + coloff4 + c] = w;
        }
    }
}

// ---------------- hash n-gram embeddings ----------------
__global__ __launch_bounds__(256) void k_hash_embed(const int* __restrict__ ids,
        const float* __restrict__ tok_emb, const float* __restrict__ hash_emb){
    int bs = blockIdx.x; int b = bs / SEQ; int i = bs - b*SEQ;
    const int* row = ids + b*SEQ;
    unsigned gg[4];
    #pragma unroll
    for (int j = 0; j < 4; j++) gg[j] = (i >= j) ? (unsigned)row[i-j] : 0u;
    const unsigned mult[3] = {2654435761u, 805459861u, 2246822519u};
    const float* src0 = tok_emb + (size_t)row[i]*DIM;
    const float* srch[3];
    #pragma unroll
    for (int f = 0; f < 3; f++){
        unsigned a = mult[f], h = 0u;
        #pragma unroll
        for (int j = 0; j < 4; j++) h = h*a + gg[j];
        srch[f] = hash_emb + ((size_t)f*32000u + (h % 32000u))*DIM;
    }
    int d = threadIdx.x*4;
    float4 v = *(const float4*)(src0 + d);
    #pragma unroll
    for (int f = 0; f < 3; f++){
        float4 w = *(const float4*)(srch[f] + d);
        v.x += w.x; v.y += w.y; v.z += w.z; v.w += w.w;
    }
    size_t o = (size_t)bs*DIM + d;
    *(float4*)(g_embeds + o) = v;
    *(float4*)(g_h + o) = v;
}

// ---------------- patch ids via warp scan (1 warp per batch) ----------------
__global__ void k_patch(const int* __restrict__ ids){
    int b = threadIdx.x >> 5;
    int lane = threadIdx.x & 31;
    if (b >= BB) return;
    const int* row = ids + b*SEQ;
    int base = 0;
    for (int c = 0; c < SEQ; c += 32){
        int i = c + lane;
        int s = (i == 0) || (row[i-1] == SPACE);
        unsigned m = __ballot_sync(0xffffffffu, s);
        int pid = base + __popc(m & (0xffffffffu >> (31 - lane))) - 1;
        g_pid[b*SEQ + i] = pid;
        if (s) g_pstart[b*SEQ + pid] = i;
        base += __popc(m);
    }
    if (lane == 0) g_np[b] = base;
}

// ---------------- rmsnorm: g_h -> g_xn (output tf32-snapped) ----------------
__global__ __launch_bounds__(256) void k_rmsnorm(const float* __restrict__ w){
    int rowi = blockIdx.x;
    int tid = threadIdx.x;
    size_t base = (size_t)rowi*DIM + tid*4;
    float4 v = *(const float4*)(g_h + base);
    float ss = v.x*v.x + v.y*v.y + v.z*v.z + v.w*v.w;
    #pragma unroll
    for (int o = 16; o; o >>= 1) ss += __shfl_xor_sync(0xffffffffu, ss, o);
    __shared__ float red[8];
    if ((tid & 31) == 0) red[tid >> 5] = ss;
    __syncthreads();
    float tot = red[0]+red[1]+red[2]+red[3]+red[4]+red[5]+red[6]+red[7];
    float r = rsqrtf(tot * (1.0f/DIM) + 1e-5f);
    float4 wv = *(const float4*)(w + tid*4);
    float4 o4;
    o4.x = rtf(v.x*r*wv.x); o4.y = rtf(v.y*r*wv.y);
    o4.z = rtf(v.z*r*wv.z); o4.w = rtf(v.w*r*wv.w);
    *(float4*)(g_xn + base) = o4;
}

#define CP_ASYNC16(dst, src) \
    asm volatile("cp.async.cg.shared.global [%0], [%1], 16;\n" :: "r"(dst), "l"(src))
#define CP_COMMIT() asm volatile("cp.async.commit_group;\n" ::)

#define MMA_TF32(acc, a0,a1,a2,a3, b0,b1) \
    asm volatile( \
        "mma.sync.aligned.m16n8k8.row.col.f32.tf32.tf32.f32 " \
        "{%0,%1,%2,%3}, {%4,%5,%6,%7}, {%8,%9}, {%0,%1,%2,%3};" \
        : "+f"((acc)[0]), "+f"((acc)[1]), "+f"((acc)[2]), "+f"((acc)[3]) \
        : "r"(a0), "r"(a1), "r"(a2), "r"(a3), "r"(b0), "r"(b1))

// ---------------- tf32 tensor-core GEMM (proven 128x128 tile) ----------------
#define GSMEM (4*(128*20 + 16*136)*4)

__global__ __launch_bounds__(256, 2) void k_gemm(const float* __restrict__ A,
        const float* __restrict__ Bm, float* __restrict__ C,
        const float* __restrict__ R, int N, int K, int addres){
    extern __shared__ __align__(16) float smem[];
    float (*As)[128][20] = (float(*)[128][20])smem;
    float (*Bs)[16][136] = (float(*)[16][136])(smem + 4*128*20);

    const int m0 = blockIdx.x * 128, n0 = blockIdx.y * 128;
    const int tid = threadIdx.x;
    const int wid = tid >> 5, lane = tid & 31;
    const int wm = (wid >> 2) * 64;
    const int wn = (wid & 3) * 32;
    const int g = lane >> 2, tg = lane & 3;

    const int arow = tid >> 2, acol = (tid & 3) * 4;
    const int brow = tid >> 5, bcol = (tid & 31) * 4;
    const float* Abase = A + (size_t)(m0 + arow)*K + acol;
    const float* Bbase = Bm + (size_t)brow*N + n0 + bcol;

    float acc[4][4][4];
    #pragma unroll
    for (int i = 0; i < 4; i++)
        #pragma unroll
        for (int j = 0; j < 4; j++)
            #pragma unroll
            for (int c = 0; c < 4; c++) acc[i][j][c] = 0.0f;

#define LOADSTAGE(st, k0) do { \
        unsigned da0 = (unsigned)__cvta_generic_to_shared(&As[st][arow][acol]); \
        CP_ASYNC16(da0, Abase + (k0)); \
        unsigned da1 = (unsigned)__cvta_generic_to_shared(&As[st][arow+64][acol]); \
        CP_ASYNC16(da1, Abase + (size_t)64*K + (k0)); \
        unsigned db0 = (unsigned)__cvta_generic_to_shared(&Bs[st][brow][bcol]); \
        CP_ASYNC16(db0, Bbase + (size_t)(k0)*N); \
        unsigned db1 = (unsigned)__cvta_generic_to_shared(&Bs[st][brow+8][bcol]); \
        CP_ASYNC16(db1, Bbase + (size_t)((k0)+8)*N); \
        CP_COMMIT(); \
    } while(0)

    const int KT = K >> 4;
    LOADSTAGE(0, 0);
    LOADSTAGE(1, 16);
    LOADSTAGE(2, 32);

    for (int kt = 0; kt < KT; kt++){
        const int s = kt & 3;
        const int rem = KT - 1 - kt;
        if (rem >= 2)      asm volatile("cp.async.wait_group 2;\n" ::);
        else if (rem == 1) asm volatile("cp.async.wait_group 1;\n" ::);
        else               asm volatile("cp.async.wait_group 0;\n" ::);
        __syncthreads();
        if (kt + 3 < KT) LOADSTAGE((kt+3) & 3, (kt+3) << 4);

        #pragma unroll
        for (int kk = 0; kk < 16; kk += 8){
            unsigned af[4][4], bf[4][2];
            #pragma unroll
            for (int i = 0; i < 4; i++){
                int r = wm + i*16;
                af[i][0] = __float_as_uint(As[s][r+g   ][kk+tg  ]);
                af[i][1] = __float_as_uint(As[s][r+g+8 ][kk+tg  ]);
                af[i][2] = __float_as_uint(As[s][r+g   ][kk+tg+4]);
                af[i][3] = __float_as_uint(As[s][r+g+8 ][kk+tg+4]);
            }
            #pragma unroll
            for (int j = 0; j < 4; j++){
                int cl = wn + j*8 + g;
                bf[j][0] = __float_as_uint(Bs[s][kk+tg  ][cl]);
                bf[j][1] = __float_as_uint(Bs[s][kk+tg+4][cl]);
            }
            #pragma unroll
            for (int i = 0; i < 4; i++)
                #pragma unroll
                for (int j = 0; j < 4; j++)
                    MMA_TF32(acc[i][j], af[i][0],af[i][1],af[i][2],af[i][3],
                             bf[j][0],bf[j][1]);
        }
    }

    #pragma unroll
    for (int i = 0; i < 4; i++){
        #pragma unroll
        for (int j = 0; j < 4; j++){
            size_t off = (size_t)(m0 + wm + i*16 + g)*N + n0 + wn + j*8 + tg*2;
            float2 r0 = make_float2(acc[i][j][0], acc[i][j][1]);
            float2 r1 = make_float2(acc[i][j][2], acc[i][j][3]);
            if (addres){
                float2 q0 = *(const float2*)(R + off);
                float2 q1 = *(const float2*)(R + off + (size_t)8*N);
                r0.x += q0.x; r0.y += q0.y; r1.x += q1.x; r1.y += q1.y;
            }
            *(float2*)(C + off) = r0;
            *(float2*)(C + off + (size_t)8*N) = r1;
        }
    }
}

// ---------------- RoPE (in place on q,k inside g_qkv) ----------------
__global__ __launch_bounds__(256) void k_rope(){
    int bs = blockIdx.x;
    int pos = bs & (SEQ - 1);
    size_t base = (size_t)bs*QKVS;
    for (int d = threadIdx.x; d < 512; d += 256){
        float freq = powf(10000.0f, -(float)d * (1.0f/512.0f));
        float ang = (float)pos * freq;
        float sn, cs;
        sincosf(ang, &sn, &cs);
        float x1 = g_qkv[base + d], x2 = g_qkv[base + 512 + d];
        g_qkv[base + d]       = x1*cs - x2*sn;
        g_qkv[base + 512 + d] = x1*sn + x2*cs;
        x1 = g_qkv[base + 1024 + d]; x2 = g_qkv[base + 1536 + d];
        g_qkv[base + 1024 + d] = x1*cs - x2*sn;
        g_qkv[base + 1536 + d] = x1*sn + x2*cs;
    }
}

// ---------------- fused windowed causal attention, 16-query tiles ----------------
// 128 threads / 4 warps; per-thread 4q x 4k (pass1) and 4q x 4n (pass2) register
// tiles: 16 FMA per 8 LDS -> LDS no longer the bottleneck.
#define QT 16
#define SPAN 544
__global__ __launch_bounds__(128) void k_attn(){
    __shared__ __align__(16) float Ssh[QT*SPAN];   // 34.8 KB
    __shared__ __align__(16) float stage[4752];    // 19 KB
    float* Qs = stage;            // [16][33]
    float* Ks = stage + 16*33;    // [128][33]
    float* Vs = stage;            // [32][136] in pass 2
    int tile = blockIdx.x;
    int b = tile / (SEQ/QT);
    int i0 = (tile - b*(SEQ/QT)) * QT;
    int tid = threadIdx.x;
    int tq = tid >> 5, tk = tid & 31;      // warp 0..3, lane
    int kmin = i0 - (WIN - 1); if (kmin < 0) kmin = 0;
    int span = i0 + QT - kmin;                       // <= 527
    int spanw = ((span + 63) >> 6) << 6;
    if (spanw > SPAN) spanw = SPAN;
    int lastkey = i0 + QT - 1;

    // ---- pass 1: scores = Q K^T / 32 (banded, masked) ----
    for (int kc0 = 0; kc0 < span; kc0 += 128){
        float c[4][4];
        #pragma unroll
        for (int u = 0; u < 4; u++)
            #pragma unroll
            for (int v = 0; v < 4; v++) c[u][v] = 0.f;
        for (int dc = 0; dc < DIM; dc += 32){
            int r = tid >> 3, cb = (tid & 7) << 2;   // r in [0,16), cb in {0..28}
            {   // Q: 16 rows x 32 cols, one float4 per thread
                float4 qv = *(const float4*)(g_qkv + ((size_t)(b*SEQ + i0 + r))*QKVS + dc + cb);
                float* qp = Qs + r*33 + cb;
                qp[0]=qv.x; qp[1]=qv.y; qp[2]=qv.z; qp[3]=qv.w;
            }
            #pragma unroll
            for (int h = 0; h < 8; h++){             // K: 128 rows
                int rr = r + h*16;
                int key = kmin + kc0 + rr; if (key > lastkey) key = lastkey;
                float4 kv = *(const float4*)(g_qkv + ((size_t)(b*SEQ + key))*QKVS + 1024 + dc + cb);
                float* kp = Ks + rr*33 + cb;
                kp[0]=kv.x; kp[1]=kv.y; kp[2]=kv.z; kp[3]=kv.w;
            }
            __syncthreads();
            #pragma unroll
            for (int d = 0; d < 32; d++){
                float a0 = Qs[(tq*4  )*33 + d];
                float a1 = Qs[(tq*4+1)*33 + d];
                float a2 = Qs[(tq*4+2)*33 + d];
                float a3 = Qs[(tq*4+3)*33 + d];
                #pragma unroll
                for (int v = 0; v < 4; v++){
                    float bv = Ks[(tk + 32*v)*33 + d];
                    c[0][v] += a0*bv;
                    c[1][v] += a1*bv;
                    c[2][v] += a2*bv;
                    c[3][v] += a3*bv;
                }
            }
            __syncthreads();
        }
        #pragma unroll
        for (int u = 0; u < 4; u++){
            int qa = i0 + tq*4 + u;
            #pragma unroll
            for (int v = 0; v < 4; v++){
                int jr = kc0 + tk + 32*v;
                if (jr < SPAN){
                    int ja = kmin + jr;
                    bool ok = (jr < span) && (ja <= qa) && (qa - ja < WIN);
                    Ssh[(tq*4+u)*SPAN + jr] = ok ? c[u][v]*0.03125f : -1e30f;
                }
            }
        }
    }
    __syncthreads();

    // ---- softmax (4 warps, 4 rows each) ----
    for (int q = tq; q < QT; q += 4){
        float* sr = Ssh + q*SPAN;
        float mx = -1e30f;
        for (int j = tk; j < spanw; j += 32) mx = fmaxf(mx, sr[j]);
        #pragma unroll
        for (int o = 16; o; o >>= 1) mx = fmaxf(mx, __shfl_xor_sync(0xffffffffu, mx, o));
        float sm = 0.f;
        for (int j = tk; j < spanw; j += 32){
            float p = expf(sr[j] - mx); sr[j] = p; sm += p;
        }
        #pragma unroll
        for (int o = 16; o; o >>= 1) sm += __shfl_xor_sync(0xffffffffu, sm, o);
        float inv = 1.0f/sm;
        for (int j = tk; j < spanw; j += 32) sr[j] *= inv;
    }
    __syncthreads();

    // ---- pass 2: O = P @ V (output tf32-snapped for the wo GEMM) ----
    for (int n0 = 0; n0 < DIM; n0 += 128){
        float o[4][4];
        #pragma unroll
        for (int u = 0; u < 4; u++)
            #pragma unroll
            for (int v = 0; v < 4; v++) o[u][v] = 0.f;
        for (int kc0 = 0; kc0 < span; kc0 += 32){
            int r = tid >> 3, cb = (tid & 7) << 4;   // 16 floats per thread
            #pragma unroll
            for (int h = 0; h < 2; h++){             // 32 rows
                int rr = r + h*16;
                int key = kmin + kc0 + rr; if (key > lastkey) key = lastkey;
                const float* vp = g_qkv + ((size_t)(b*SEQ + key))*QKVS + 2048 + n0 + cb;
                #pragma unroll
                for (int t4 = 0; t4 < 4; t4++){
                    *(float4*)(Vs + rr*136 + cb + t4*4) = *(const float4*)(vp + t4*4);
                }
            }
            __syncthreads();
            const float* p0r = Ssh + (tq*4)*SPAN + kc0;
            #pragma unroll
            for (int jj = 0; jj < 32; jj++){
                float p0 = p0r[jj];
                float p1 = p0r[jj + SPAN];
                float p2 = p0r[jj + 2*SPAN];
                float p3 = p0r[jj + 3*SPAN];
                #pragma unroll
                for (int v = 0; v < 4; v++){
                    float vv = Vs[jj*136 + tk + 32*v];
                    o[0][v] += p0*vv;
                    o[1][v] += p1*vv;
                    o[2][v] += p2*vv;
                    o[3][v] += p3*vv;
                }
            }
            __syncthreads();
        }
        #pragma unroll
        for (int u = 0; u < 4; u++){
            size_t ob = ((size_t)(b*SEQ + i0 + tq*4 + u))*DIM + n0;
            #pragma unroll
            for (int v = 0; v < 4; v++)
                g_attn[ob + tk + 32*v] = rtf(o[u][v]);
        }
    }
}

// ---------------- silu(f13[:, :FF]) * f13[:, FF:] -> f1 (tf32-snapped) ----------------
__global__ __launch_bounds__(704) void k_silu(){
    int row = blockIdx.x;
    int col = threadIdx.x * 4;
    size_t src = (size_t)row*FF2 + col;
    float4 a = *(float4*)(g_f13 + src);
    float4 c = *(float4*)(g_f13 + src + FF);
    a.x = rtf(a.x/(1.f + expf(-a.x))*c.x);
    a.y = rtf(a.y/(1.f + expf(-a.y))*c.y);
    a.z = rtf(a.z/(1.f + expf(-a.z))*c.z);
    a.w = rtf(a.w/(1.f + expf(-a.w))*c.w);
    *(float4*)(g_f1 + (size_t)row*FF + col) = a;
}

// ---------------- segment max pooling (runs are contiguous) ----------------
__global__ __launch_bounds__(256) void k_pool(){
    int b = blockIdx.y, p = blockIdx.x;
    int np = g_np[b];
    if (p >= np) return;
    int i0 = g_pstart[b*SEQ + p];
    int i1 = (p + 1 < np) ? g_pstart[b*SEQ + p + 1] : SEQ;
    int d = threadIdx.x*4;
    float4 m = make_float4(-FLT_MAX, -FLT_MAX, -FLT_MAX, -FLT_MAX);
    const float* src = g_xn + (size_t)b*SEQ*DIM + d;
    for (int i = i0; i < i1; i++){
        float4 v = *(const float4*)(src + (size_t)i*DIM);
        m.x = fmaxf(m.x, v.x); m.y = fmaxf(m.y, v.y);
        m.z = fmaxf(m.z, v.z); m.w = fmaxf(m.w, v.w);
    }
    *(float4*)(g_pool + ((size_t)(b*SEQ + p))*DIM + d) = m;
}

// ---------------- hd = embeds + pooled[pid]  -> g_h ----------------
__global__ __launch_bounds__(256) void k_gather(){
    int bs = blockIdx.x; int b = bs / SEQ;
    int pid = g_pid[bs];
    int d = threadIdx.x*4;
    size_t o = (size_t)bs*DIM + d;
    float4 e = *(const float4*)(g_embeds + o);
    float4 pl = *(const float4*)(g_pool + ((size_t)(b*SEQ + pid))*DIM + d);
    e.x += pl.x; e.y += pl.y; e.z += pl.z; e.w += pl.w;
    *(float4*)(g_h + o) = e;
}

// ---------------- host orchestration ----------------
extern "C" void kernel_launch(void* const* d_in, const int* in_sizes, int n_in,
                              void* d_out, int out_size){
    const int*   ids  = (const int*)d_in[0];
    const float* tok  = (const float*)d_in[1];
    const float* hemb = (const float*)d_in[2];

    float *p_xn, *p_qkv, *p_attn, *p_h, *p_f13, *p_f1, *p_wt;
    cudaGetSymbolAddress((void**)&p_xn,   g_xn);
    cudaGetSymbolAddress((void**)&p_qkv,  g_qkv);
    cudaGetSymbolAddress((void**)&p_attn, g_attn);
    cudaGetSymbolAddress((void**)&p_h,    g_h);
    cudaGetSymbolAddress((void**)&p_f13,  g_f13);
    cudaGetSymbolAddress((void**)&p_f1,   g_f1);
    cudaGetSymbolAddress((void**)&p_wt,   g_wt);

    static int smem_set = 0;
    if (!smem_set){
        cudaFuncSetAttribute(k_gemm, cudaFuncAttributeMaxDynamicSharedMemorySize, GSMEM);
        smem_set = 1;
    }

    // Round weights to tf32-snapped scratch; pack qkv -> [1024,3072], w1|w3 -> [1024,5632].
    #define RND(src, dstoff, ncols, totcols, coloff, nelem) do { \
        int _n4 = (nelem)/4; \
        int _grid = (_n4 + 256*4 - 1)/(256*4); \
        k_round<<<_grid, 256>>>((src), p_wt + (dstoff), _n4, (ncols)/4, (totcols)/4, (coloff)/4); \
    } while(0)
    for (int L = 0; L < 2; L++){
        size_t base = (size_t)L*LWS;
        RND((const float*)d_in[3+10*L+0], base,            DIM, QKVS, 0,        DD);  // wq
        RND((const float*)d_in[3+10*L+1], base,            DIM, QKVS, DIM,      DD);  // wk
        RND((const float*)d_in[3+10*L+2], base,            DIM, QKVS, 2*DIM,    DD);  // wv
        RND((const float*)d_in[3+10*L+3], base+3*DD,       DIM, DIM,  0,        DD);  // wo
        RND((const float*)d_in[3+10*L+4], base+4*DD,       FF,  FF2,  0,        DF);  // w1
        RND((const float*)d_in[3+10*L+6], base+4*DD,       FF,  FF2,  FF,       DF);  // w3
        RND((const float*)d_in[3+10*L+5], base+4*DD+2*(size_t)DF, DIM, DIM, 0,  DF);  // w2
    }
    RND((const float*)d_in[23], 2*(size_t)LWS, OUTV, OUTV, 0, (size_t)DIM*OUTV);

    k_hash_embed<<<NTOK, 256>>>(ids, tok, hemb);
    k_patch<<<1, 64>>>(ids);

    for (int L = 0; L < 2; L++){
        size_t base = (size_t)L*LWS;
        float* wqkv = p_wt + base;
        float* wo   = p_wt + base + 3*DD;
        float* w13  = p_wt + base + 4*DD;
        float* w2   = p_wt + base + 4*DD + 2*(size_t)DF;
        const float* natt = (const float*)d_in[3 + 10*L + 7];
        const float* nffn = (const float*)d_in[3 + 10*L + 8];
        const float* nout = (const float*)d_in[3 + 10*L + 9];

        k_rmsnorm<<<NTOK, 256>>>(natt);
        k_gemm<<<dim3(32, 24), 256, GSMEM>>>(p_xn, wqkv, p_qkv, nullptr, QKVS, DIM, 0);
        k_rope<<<NTOK, 256>>>();
        k_attn<<<NTOK/QT, 128>>>();
        k_gemm<<<dim3(32, 8),  256, GSMEM>>>(p_attn, wo, p_h, p_h, DIM, DIM, 1);
        k_rmsnorm<<<NTOK, 256>>>(nffn);
        k_gemm<<<dim3(32, 44), 256, GSMEM>>>(p_xn, w13, p_f13, nullptr, FF2, DIM, 0);
        k_silu<<<NTOK, 704>>>();
        k_gemm<<<dim3(32, 8),  256, GSMEM>>>(p_f1, w2, p_h, p_h, DIM, FF, 1);

        if (L == 0){
            k_rmsnorm<<<NTOK, 256>>>(nout);        // g_h -> g_xn (encoder out norm)
            k_pool<<<dim3(SEQ, BB), 256>>>();      // segment max over g_xn
            k_gather<<<NTOK, 256>>>();             // g_h = embeds + pooled[pid]
        }
    }
    k_rmsnorm<<<NTOK, 256>>>((const float*)d_in[22]);  // dec_norm_out
    k_gemm<<<dim3(32, 250), 256, GSMEM>>>(p_xn, p_wt + 2*(size_t)LWS, (float*)d_out,
                                          nullptr, OUTV, DIM, 0);
}